// round 7
// baseline (speedup 1.0000x reference)
#include <cuda_runtime.h>

#define T25   25
#define HID   100
#define G4    400
#define NROWS 12800           // 512*25

typedef unsigned long long u64;

__device__ float g_zx1[(size_t)NROWS * G4];   // layer1 input projection (incl b1)
__device__ float g_z2x[(size_t)NROWS * G4];   // layer2 input projection (incl b2)
__device__ float g_h1 [(size_t)NROWS * HID];  // layer1 hidden states, all t

union U4 { float4 f4; ulonglong2 u2; };
union U2 { float2 f2; u64 u; };

__device__ __forceinline__ u64 pk(float lo, float hi) {
    u64 r; asm("mov.b64 %0, {%1,%2};" : "=l"(r) : "f"(lo), "f"(hi)); return r;
}
__device__ __forceinline__ void ffma2(u64& d, u64 a, u64 b) {
    asm("fma.rn.f32x2 %0, %1, %2, %0;" : "+l"(d) : "l"(a), "l"(b));
}
__device__ __forceinline__ float hsum(u64 v) {
    float a, b; asm("mov.b64 {%0,%1}, %2;" : "=f"(a), "=f"(b) : "l"(v)); return a + b;
}
__device__ __forceinline__ float sigm(float x)   { return 1.0f / (1.0f + __expf(-x)); }
__device__ __forceinline__ float mytanh(float x) { float e = __expf(-2.0f * x); return (1.0f - e) / (1.0f + e); }

// ---------------------------------------------------------------------------
// Input-projection GEMM (unchanged from best config):
// out[row][c] = bias[c] + sum_k src(row)[k] * W[k][c], W staged in smem.
// ---------------------------------------------------------------------------
#define IP_SMEM_B ((HID * G4 + HID * 104) * 4)   // 201600 bytes

template<int NQ>
__device__ __forceinline__ void inproj_main(
    const float (*xs)[104], const float* __restrict__ wsm,
    int c, int rb, float bv, float* __restrict__ out, int row0)
{
    u64 acc[2 * NQ];
    u64 binit = pk(bv, bv);
    #pragma unroll
    for (int p = 0; p < 2 * NQ; p++) acc[p] = binit;

    #pragma unroll 2
    for (int k = 0; k < HID; k++) {
        float w = wsm[k * G4 + c];
        u64 wd = pk(w, w);
        const float* xr = &xs[k][rb];
        #pragma unroll
        for (int q = 0; q < NQ; q++) {
            U4 x; x.f4 = *(const float4*)(xr + 4 * q);
            ffma2(acc[2 * q],     x.u2.x, wd);
            ffma2(acc[2 * q + 1], x.u2.y, wd);
        }
    }
    #pragma unroll
    for (int p = 0; p < 2 * NQ; p++) {
        U2 v; v.u = acc[p];
        out[(long long)(row0 + rb + 2 * p) * G4 + c]     = v.f2.x;
        out[(long long)(row0 + rb + 2 * p + 1) * G4 + c] = v.f2.y;
    }
}

__global__ void __launch_bounds__(800, 1) inproj_kernel(
    const float* __restrict__ src,    // [12800][100] or null (then gather emb)
    const int*   __restrict__ feats,  // [12800] or null
    const float* __restrict__ emb,    // [VOCAB][100]
    const float* __restrict__ W,      // [100][400]
    const float* __restrict__ bias,   // [400]
    float*       __restrict__ out)    // [12800][400]
{
    extern __shared__ __align__(16) float smp[];
    float* wsm = smp;                              // [100*400]
    float (*xs)[104] = (float(*)[104])(smp + HID * G4);

    const int tid  = threadIdx.x;
    const int row0 = blockIdx.x * 100;

    for (int i4 = tid; i4 < HID * G4 / 4; i4 += 800)
        ((float4*)wsm)[i4] = ((const float4*)W)[i4];

    for (int idx = tid; idx < 25 * 100; idx += 800) {
        int j4 = idx / 100, rl = idx % 100;
        const float* base = feats
            ? emb + (long long)__ldg(feats + row0 + rl) * HID
            : src + (long long)(row0 + rl) * HID;
        float4 v = *(const float4*)(base + 4 * j4);
        xs[4 * j4 + 0][rl] = v.x;
        xs[4 * j4 + 1][rl] = v.y;
        xs[4 * j4 + 2][rl] = v.z;
        xs[4 * j4 + 3][rl] = v.w;
    }
    __syncthreads();

    const int c  = tid % G4;
    const int rg = tid / G4;
    const float bv = bias[c];
    if (rg == 0) inproj_main<13>(xs, wsm, c, 0,  bv, out, row0);
    else         inproj_main<12>(xs, wsm, c, 52, bv, out, row0);
}

// ---------------------------------------------------------------------------
// Recurrence kernel v2: warp-local reduction + gates, ONE barrier per step.
// 416 threads = 13 warps. lane = 4*q + 2*ch + kh; unit u = 8*wid + q
// (u in [0,104); u>=100 lanes are padding). Thread handles 2 gate-cols of
// unit u (ch selects {u,u+100} or {u+200,u+300}) over k-half kh, all 4 rows.
// Weights register-resident (52 u64). k-reduce: shfl_xor 1. Gate math split
// across ch lanes, joined by shfl_xor 2. h -> smem, one __syncthreads.
// ---------------------------------------------------------------------------
#define RT 416

__global__ void __launch_bounds__(RT, 1) rec_kernel(
    const float* __restrict__ zin,    // [12800][400]  (x-proj incl bias)
    const float* __restrict__ Wh,     // [100][400]
    float*       __restrict__ h_out,  // [12800][100] or null
    const float* __restrict__ wfc1, const float* __restrict__ bfc1,
    const float* __restrict__ wfc2, const float* __restrict__ bfc2,
    float*       __restrict__ out)    // [512][2] or null
{
    __shared__ __align__(16) float hs[4][104];      // h state, zero-padded
    __shared__ float fc1s[4][128];

    const int tid  = threadIdx.x;
    const int b0   = blockIdx.x * 4;
    const int lane = tid & 31;
    const int wid  = tid >> 5;
    const int u    = wid * 8 + (lane >> 2);          // 0..103
    const int ch   = (lane >> 1) & 1;
    const int kh   = lane & 1;
    const bool act = (u < HID);

    const int c0 = u + 200 * ch;                     // gate cols of this lane
    const int c1 = u + 100 + 200 * ch;

    // ---- register-resident weights: 2 cols x 52 k (k-pairs) ----
    u64 wp[26], wq[26];
    #pragma unroll
    for (int j = 0; j < 26; j++) {
        int k = kh * 52 + 2 * j;
        float p0 = 0.f, p1 = 0.f, q0 = 0.f, q1 = 0.f;
        if (act && k < HID)     { p0 = __ldg(Wh + k * G4 + c0);       q0 = __ldg(Wh + k * G4 + c1); }
        if (act && k + 1 < HID) { p1 = __ldg(Wh + (k + 1) * G4 + c0); q1 = __ldg(Wh + (k + 1) * G4 + c1); }
        wp[j] = pk(p0, p1);
        wq[j] = pk(q0, q1);
    }
    for (int i = tid; i < 4 * 104; i += RT) ((float*)hs)[i] = 0.f;
    __syncthreads();

    // zin values folded into acc init: kh=0 owns rows 0,1; kh=1 rows 2,3
    const float* zbase = zin + ((long long)(b0 + 2 * kh) * T25) * G4;
    float za0 = 0.f, za1 = 0.f, za2 = 0.f, za3 = 0.f;   // (r,c0),(r,c1),(r+1,c0),(r+1,c1)
    if (act) {
        za0 = __ldg(zbase + c0);
        za1 = __ldg(zbase + c1);
        za2 = __ldg(zbase + T25 * G4 + c0);
        za3 = __ldg(zbase + T25 * G4 + c1);
    }

    float cst[4] = {0.f, 0.f, 0.f, 0.f};   // cell state (valid in ch==1 lanes)
    float z0[4], z1[4];                     // z partial/full for cols c0,c1 per row

    for (int t = 0; t < T25; t++) {
        // ---- GEMM: rows 0..3, my k-half, cols c0,c1 ----
        #pragma unroll
        for (int r = 0; r < 4; r++) {
            // fold zin into the row owned by my kh ((r>>1)==kh)
            u64 a0, a1;
            if ((r >> 1) == kh) {
                a0 = pk((r & 1) ? za2 : za0, 0.f);
                a1 = pk((r & 1) ? za3 : za1, 0.f);
            } else { a0 = 0ULL; a1 = 0ULL; }

            const float4* hv = (const float4*)&hs[r][0];
            #pragma unroll
            for (int j = 0; j < 13; j++) {
                U4 h; h.f4 = hv[kh * 13 + j];
                ffma2(a0, h.u2.x, wp[2 * j]);
                ffma2(a1, h.u2.x, wq[2 * j]);
                ffma2(a0, h.u2.y, wp[2 * j + 1]);
                ffma2(a1, h.u2.y, wq[2 * j + 1]);
            }
            z0[r] = hsum(a0);
            z1[r] = hsum(a1);
        }

        // prefetch zin for step t+1 (consumed next iteration)
        if (t + 1 < T25 && act) {
            const float* zb = zbase + (t + 1) * G4;
            za0 = __ldg(zb + c0);
            za1 = __ldg(zb + c1);
            za2 = __ldg(zb + T25 * G4 + c0);
            za3 = __ldg(zb + T25 * G4 + c1);
        }

        // ---- k-half reduction (in-warp) ----
        #pragma unroll
        for (int r = 0; r < 4; r++) {
            z0[r] += __shfl_xor_sync(0xffffffffu, z0[r], 1);
            z1[r] += __shfl_xor_sync(0xffffffffu, z1[r], 1);
        }

        // ---- gates, split across ch lanes ----
        float gv0[4], gv1[4];
        if (ch == 0) {          // has zi (c0=u), zj (c1=u+100)
            #pragma unroll
            for (int r = 0; r < 4; r++) gv0[r] = sigm(z0[r]) * mytanh(z1[r]);   // gin
        } else {                // has zf (u+200), zo (u+300)
            #pragma unroll
            for (int r = 0; r < 4; r++) {
                gv0[r] = sigm(z0[r] + 1.0f);   // gf
                gv1[r] = sigm(z1[r]);          // go
            }
        }
        #pragma unroll
        for (int r = 0; r < 4; r++) {
            float gin = __shfl_xor_sync(0xffffffffu, gv0[r], 2);  // ch1 receives gin
            if (ch == 1) {
                float cv = cst[r] * gv0[r] + gin;
                cst[r] = cv;
                float hn = mytanh(cv) * gv1[r];
                if (kh == 0 && act) {
                    hs[r][u] = hn;
                    if (h_out)
                        h_out[((long long)(b0 + r) * T25 + t) * HID + u] = hn;
                }
            }
        }
        __syncthreads();
    }

    // ---- FC head (layer-2 kernel only) ----
    if (out) {
        for (int idx = tid; idx < 4 * 128; idx += RT) {
            int r = idx / 128, j = idx % 128;
            float a = bfc1[j];
            #pragma unroll 4
            for (int k = 0; k < HID; k++)
                a += hs[r][k] * __ldg(wfc1 + k * 128 + j);
            fc1s[r][j] = a;
        }
        __syncthreads();
        if (tid < 8) {
            int r = tid / 2, cc = tid % 2;
            float a = bfc2[cc];
            #pragma unroll 8
            for (int k = 0; k < 128; k++)
                a += fc1s[r][k] * __ldg(wfc2 + k * 2 + cc);
            out[(b0 + r) * 2 + cc] = a;
        }
    }
}

// ---------------------------------------------------------------------------
extern "C" void kernel_launch(void* const* d_in, const int* in_sizes, int n_in,
                              void* d_out, int out_size)
{
    const int*   feats = (const int*)  d_in[0];
    const float* emb   = (const float*)d_in[1];
    const float* k1    = (const float*)d_in[2];
    const float* b1    = (const float*)d_in[3];
    const float* k2    = (const float*)d_in[4];
    const float* b2    = (const float*)d_in[5];
    const float* wfc1  = (const float*)d_in[6];
    const float* bfc1  = (const float*)d_in[7];
    const float* wfc2  = (const float*)d_in[8];
    const float* bfc2  = (const float*)d_in[9];
    float* out = (float*)d_out;

    float *zx1, *z2x, *h1;
    cudaGetSymbolAddress((void**)&zx1, g_zx1);
    cudaGetSymbolAddress((void**)&z2x, g_z2x);
    cudaGetSymbolAddress((void**)&h1,  g_h1);

    cudaFuncSetAttribute(inproj_kernel,
                         cudaFuncAttributeMaxDynamicSharedMemorySize, IP_SMEM_B);

    // A: zx1 = emb[feats] @ k1[0:100] + b1
    inproj_kernel<<<128, 800, IP_SMEM_B>>>(nullptr, feats, emb, k1, b1, zx1);
    // B: layer-1 recurrence -> h1 (all timesteps)
    rec_kernel<<<128, RT>>>(zx1, k1 + HID * G4, h1,
                            nullptr, nullptr, nullptr, nullptr, nullptr);
    // C: z2x = h1 @ k2[0:100] + b2
    inproj_kernel<<<128, 800, IP_SMEM_B>>>(h1, nullptr, nullptr, k2, b2, z2x);
    // D: layer-2 recurrence + FC head -> out
    rec_kernel<<<128, RT>>>(z2x, k2 + HID * G4, nullptr,
                            wfc1, bfc1, wfc2, bfc2, out);
}